// round 1
// baseline (speedup 1.0000x reference)
#include <cuda_runtime.h>
#include <cuda_bf16.h>

#define BS 16
#define NQ 300
#define NT 50
#define KP3 51          // 17 keypoints * 3
#define NCOL (BS*NT)    // 800  (all targets across batches)
#define NROW (BS*NQ)    // 4800 (all queries across batches)

// -------- device scratch (no allocations allowed) --------
__device__ float g_distkp[NCOL*KP3];   // normalized target keypoints
__device__ float g_tmin[NCOL*3];       // target box xyz min
__device__ float g_tmax[NCOL*3];       // target box xyz max
__device__ float g_tvol[NCOL];         // target box volume
__device__ float g_lap[BS*NT*NQ];      // per-batch transposed cost [b][t][q]

// ---------------------------------------------------------
// Kernel 1: preprocess targets
// ---------------------------------------------------------
__global__ void prep_kernel(const float* __restrict__ tgt_boxes,
                            const float* __restrict__ tgt_kp) {
    int t = blockIdx.x * blockDim.x + threadIdx.x;
    if (t >= NCOL) return;
    float c0 = tgt_boxes[t*6+0], c1 = tgt_boxes[t*6+1], c2 = tgt_boxes[t*6+2];
    float s0 = tgt_boxes[t*6+3], s1 = tgt_boxes[t*6+4], s2 = tgt_boxes[t*6+5];
    float m0 = c0 - 0.5f*s0, m1 = c1 - 0.5f*s1, m2 = c2 - 0.5f*s2;
    float M0 = c0 + 0.5f*s0, M1 = c1 + 0.5f*s1, M2 = c2 + 0.5f*s2;
    g_tmin[t*3+0] = m0; g_tmin[t*3+1] = m1; g_tmin[t*3+2] = m2;
    g_tmax[t*3+0] = M0; g_tmax[t*3+1] = M1; g_tmax[t*3+2] = M2;
    g_tvol[t] = (M0-m0)*(M1-m1)*(M2-m2);
    #pragma unroll
    for (int k = 0; k < 17; k++) {
        g_distkp[t*KP3 + k*3 + 0] = (tgt_kp[t*KP3 + k*3 + 0] - m0) / s0;
        g_distkp[t*KP3 + k*3 + 1] = (tgt_kp[t*KP3 + k*3 + 1] - m1) / s1;
        g_distkp[t*KP3 + k*3 + 2] = (tgt_kp[t*KP3 + k*3 + 2] - m2) / s2;
    }
}

// ---------------------------------------------------------
// Kernel 2: full cost matrix C[4800][800] + per-batch LAP staging
// grid = (ceil(800/256), 4800), block = 256
// ---------------------------------------------------------
__global__ void cost_kernel(const float* __restrict__ pkp,
                            const float* __restrict__ pbox,
                            float* __restrict__ C) {
    __shared__ float skp[KP3];
    __shared__ float sb[6];
    int r = blockIdx.y;
    int tid = threadIdx.x;
    if (tid < KP3) skp[tid] = pkp[r*KP3 + tid];
    else if (tid < KP3 + 6) sb[tid - KP3] = pbox[r*6 + tid - KP3];
    __syncthreads();

    int c = blockIdx.x * blockDim.x + tid;
    if (c >= NCOL) return;

    // keypoint L1 cost
    float s = 0.f;
    const float* dk = &g_distkp[c*KP3];
    #pragma unroll
    for (int k = 0; k < KP3; k++) s += fabsf(skp[k] - dk[k]);

    // GIoU
    float pmin[3], pmax[3];
    #pragma unroll
    for (int d = 0; d < 3; d++) {
        pmin[d] = sb[d] - 0.5f*sb[3+d];
        pmax[d] = sb[d] + 0.5f*sb[3+d];
    }
    float vol1 = (pmax[0]-pmin[0])*(pmax[1]-pmin[1])*(pmax[2]-pmin[2]);
    float vol2 = g_tvol[c];
    float inter = 1.f, evol = 1.f;
    #pragma unroll
    for (int d = 0; d < 3; d++) {
        float tmn = g_tmin[c*3+d], tmx = g_tmax[c*3+d];
        float lt = fmaxf(pmin[d], tmn), rb = fminf(pmax[d], tmx);
        inter *= fmaxf(rb - lt, 0.f);
        float el = fminf(pmin[d], tmn), er = fmaxf(pmax[d], tmx);
        evol *= fmaxf(er - el, 0.f);
    }
    float uni  = vol1 + vol2 - inter;
    float giou = inter/uni - (evol - uni)/evol;
    float cost = s - giou;

    C[(size_t)r*NCOL + c] = cost;

    // stage diagonal-block cost transposed: lap[b][t][q]
    int b = r / NQ;
    int c0 = b * NT;
    if (c >= c0 && c < c0 + NT) {
        g_lap[((size_t)b*NT + (c - c0))*NQ + (r - b*NQ)] = cost;
    }
}

// ---------------------------------------------------------
// Kernel 3: Jonker-Volgenant shortest augmenting path LAP
// one block per batch, 256 threads; fp64 state to mirror numpy reference
// ---------------------------------------------------------
__global__ void __launch_bounds__(256) lap_kernel(float* __restrict__ out) {
    const int b   = blockIdx.x;
    const int tid = threadIdx.x;
    const int BD  = 256;
    const int lane = tid & 31;
    const int wid  = tid >> 5;
    const float* lc = &g_lap[(size_t)b*NT*NQ];
    const double INF = 1e300;

    __shared__ double u[NT], v[NQ], shortest[NQ];
    __shared__ int path[NQ], row4col[NQ], col4row[NT];
    __shared__ unsigned char SC[NQ], SR[NT];
    __shared__ double wval[8];
    __shared__ int widx[8];
    __shared__ double sh_minVal;
    __shared__ int sh_i, sh_sink;

    for (int j = tid; j < NQ; j += BD) { v[j] = 0.0; row4col[j] = -1; }
    if (tid < NT) { u[tid] = 0.0; col4row[tid] = -1; }
    __syncthreads();

    for (int curRow = 0; curRow < NT; curRow++) {
        for (int j = tid; j < NQ; j += BD) { shortest[j] = INF; path[j] = -1; SC[j] = 0; }
        if (tid < NT) SR[tid] = 0;
        if (tid == 0) { sh_minVal = 0.0; sh_i = curRow; sh_sink = -1; }
        __syncthreads();

        while (true) {
            if (tid == 0) SR[sh_i] = 1;
            __syncthreads();                       // B1
            const int i = sh_i;
            const double mv = sh_minVal;
            const double ui = u[i];
            const float* lrow = lc + i*NQ;
            for (int j = tid; j < NQ; j += BD) {
                if (!SC[j]) {
                    double rr = mv + (double)lrow[j] - ui - v[j];
                    if (rr < shortest[j]) { shortest[j] = rr; path[j] = i; }
                }
            }
            __syncthreads();                       // B2

            // argmin over uncovered columns, ties -> lowest index (np.argmin)
            double bv = INF * 2.0; int bi = NQ;
            for (int j = tid; j < NQ; j += BD) {
                if (!SC[j]) {
                    double sv = shortest[j];
                    if (sv < bv) { bv = sv; bi = j; }   // ascending j => first-min kept
                }
            }
            #pragma unroll
            for (int off = 16; off; off >>= 1) {
                double ov = __shfl_down_sync(0xffffffffu, bv, off);
                int    oi = __shfl_down_sync(0xffffffffu, bi, off);
                if (ov < bv || (ov == bv && oi < bi)) { bv = ov; bi = oi; }
            }
            if (lane == 0) { wval[wid] = bv; widx[wid] = bi; }
            __syncthreads();                       // B3
            if (tid == 0) {
                double fv = wval[0]; int fi = widx[0];
                #pragma unroll
                for (int w = 1; w < 8; w++) {
                    double ov = wval[w]; int oi = widx[w];
                    if (ov < fv || (ov == fv && oi < fi)) { fv = ov; fi = oi; }
                }
                sh_minVal = fv;
                SC[fi] = 1;
                if (row4col[fi] == -1) sh_sink = fi;
                else                   sh_i    = row4col[fi];
            }
            __syncthreads();                       // B4
            if (sh_sink != -1) break;
        }

        // dual updates (pre-augmentation state, like the reference)
        const double mv = sh_minVal;
        if (tid < NT) {
            if (tid == curRow)      u[tid] += mv;
            else if (SR[tid])       u[tid] += mv - shortest[col4row[tid]];
        }
        for (int j = tid; j < NQ; j += BD)
            if (SC[j]) v[j] -= mv - shortest[j];
        __syncthreads();

        // augment (serial, tiny)
        if (tid == 0) {
            int j = sh_sink;
            while (true) {
                int i = path[j];
                row4col[j] = i;
                int nj = col4row[i];
                col4row[i] = j;
                j = nj;
                if (i == curRow) break;
            }
        }
        __syncthreads();
    }

    // emit indices: sort (query, target) pairs by query via rank counting.
    // reference: i = sorted assigned queries, j = corresponding targets
    if (tid < NT) {
        int q = col4row[tid];
        int rank = 0;
        #pragma unroll
        for (int t2 = 0; t2 < NT; t2++) rank += (col4row[t2] < q) ? 1 : 0;
        size_t base = (size_t)NROW * NCOL + (size_t)b * 2 * NT;
        out[base + rank]      = (float)q;    // indices[b][0][rank]
        out[base + NT + rank] = (float)tid;  // indices[b][1][rank]
    }
}

// ---------------------------------------------------------
extern "C" void kernel_launch(void* const* d_in, const int* in_sizes, int n_in,
                              void* d_out, int out_size) {
    const float* pred_kp   = (const float*)d_in[0];  // (16,300,51)
    const float* pred_box  = (const float*)d_in[1];  // (16,300,6)
    const float* tgt_box   = (const float*)d_in[2];  // (16,50,6)
    const float* tgt_kp    = (const float*)d_in[3];  // (16,50,51)
    float* out = (float*)d_out;

    prep_kernel<<<(NCOL + 255) / 256, 256>>>(tgt_box, tgt_kp);

    dim3 cg((NCOL + 255) / 256, NROW);
    cost_kernel<<<cg, 256>>>(pred_kp, pred_box, out);

    lap_kernel<<<BS, 256>>>(out);
}

// round 2
// speedup vs baseline: 3.5909x; 3.5909x over previous
#include <cuda_runtime.h>
#include <cuda_bf16.h>

#define BS 16
#define NQ 300
#define NT 50
#define KP3 51          // 17 keypoints * 3
#define NCOL (BS*NT)    // 800
#define NROW (BS*NQ)    // 4800
#define NK 10           // columns per lane in LAP (10*32 >= 300)

// -------- device scratch (SoA, coalesced) --------
__device__ float g_distkp[KP3][NCOL];  // normalized target keypoints, k-major
__device__ float g_tmin[3][NCOL];
__device__ float g_tmax[3][NCOL];
__device__ float g_tvol[NCOL];
__device__ float g_lap[BS*NT*NQ];      // per-batch transposed cost [b][t][q]

// ---------------------------------------------------------
// Kernel 1: preprocess targets (one thread per (t,k) keypoint coord)
// ---------------------------------------------------------
__global__ void prep_kernel(const float* __restrict__ tgt_boxes,
                            const float* __restrict__ tgt_kp) {
    int idx = blockIdx.x * blockDim.x + threadIdx.x;
    if (idx < NCOL * KP3) {
        int t = idx / KP3, k = idx % KP3, d = k % 3;
        float c = tgt_boxes[t*6 + d];
        float s = tgt_boxes[t*6 + 3 + d];
        g_distkp[k][t] = (tgt_kp[idx] - (c - 0.5f*s)) / s;
    }
    if (idx < NCOL) {
        int t = idx;
        float e0 = 0.f, e1 = 0.f, e2 = 0.f;
        #pragma unroll
        for (int d = 0; d < 3; d++) {
            float c = tgt_boxes[t*6 + d];
            float s = tgt_boxes[t*6 + 3 + d];
            float m = c - 0.5f*s, M = c + 0.5f*s;
            g_tmin[d][t] = m; g_tmax[d][t] = M;
            if (d == 0) e0 = M - m; else if (d == 1) e1 = M - m; else e2 = M - m;
        }
        g_tvol[t] = e0*e1*e2;
    }
}

// ---------------------------------------------------------
// Kernel 2: cost matrix C[4800][800], all target reads coalesced
// grid = (ceil(800/256), 4800), block = 256
// ---------------------------------------------------------
__global__ void cost_kernel(const float* __restrict__ pkp,
                            const float* __restrict__ pbox,
                            float* __restrict__ C) {
    __shared__ float skp[KP3];
    __shared__ float sb[6];
    int r = blockIdx.y;
    int tid = threadIdx.x;
    if (tid < KP3) skp[tid] = pkp[r*KP3 + tid];
    else if (tid < KP3 + 6) sb[tid - KP3] = pbox[r*6 + tid - KP3];
    __syncthreads();

    int c = blockIdx.x * blockDim.x + tid;
    if (c >= NCOL) return;

    // keypoint L1 cost (coalesced k-major reads)
    float s = 0.f;
    #pragma unroll
    for (int k = 0; k < KP3; k++) s += fabsf(skp[k] - g_distkp[k][c]);

    // GIoU
    float pmin[3], pmax[3];
    #pragma unroll
    for (int d = 0; d < 3; d++) {
        pmin[d] = sb[d] - 0.5f*sb[3+d];
        pmax[d] = sb[d] + 0.5f*sb[3+d];
    }
    float vol1 = (pmax[0]-pmin[0])*(pmax[1]-pmin[1])*(pmax[2]-pmin[2]);
    float vol2 = g_tvol[c];
    float inter = 1.f, evol = 1.f;
    #pragma unroll
    for (int d = 0; d < 3; d++) {
        float tmn = g_tmin[d][c], tmx = g_tmax[d][c];
        inter *= fmaxf(fminf(pmax[d], tmx) - fmaxf(pmin[d], tmn), 0.f);
        evol  *= fmaxf(fmaxf(pmax[d], tmx) - fminf(pmin[d], tmn), 0.f);
    }
    float uni  = vol1 + vol2 - inter;
    float cost = s - (inter/uni - (evol - uni)/evol);

    C[(size_t)r*NCOL + c] = cost;

    // stage diagonal-block cost transposed: lap[b][t][q]
    int b = r / NQ;
    int c0 = b * NT;
    if (c >= c0 && c < c0 + NT) {
        g_lap[((size_t)b*NT + (c - c0))*NQ + (r - b*NQ)] = cost;
    }
}

// ---------------------------------------------------------
// Kernel 3: shortest augmenting path LAP, ONE WARP per batch.
// Lane owns columns j = k*32 + lane (k<NK). shortest/v/SC in registers.
// Dual updates reconstructed from selection log (selj, selv):
//   for covered col j, shortest[j] == minVal at j's selection step.
// ---------------------------------------------------------
__global__ void __launch_bounds__(32) lap_kernel(float* __restrict__ out) {
    const int b    = blockIdx.x;
    const int lane = threadIdx.x;
    const float* lc = &g_lap[(size_t)b*NT*NQ];
    const float INF = 3.0e38f;

    __shared__ float u[NT];
    __shared__ int   path[NQ];
    __shared__ int   row4col[NQ];
    __shared__ int   col4row[NT];
    __shared__ int   selj[NQ + 2];
    __shared__ float selv[NQ + 2];

    float shortest[NK];
    float vloc[NK];

    for (int j = lane; j < NQ; j += 32) row4col[j] = -1;
    for (int t = lane; t < NT; t += 32) { u[t] = 0.f; col4row[t] = -1; }
    #pragma unroll
    for (int k = 0; k < NK; k++) vloc[k] = 0.f;
    __syncwarp();

    for (int curRow = 0; curRow < NT; curRow++) {
        #pragma unroll
        for (int k = 0; k < NK; k++) shortest[k] = INF;
        unsigned sc = 0;           // covered bit per k (this lane's columns)
        int   i  = curRow;
        float mv = 0.f;
        int   nsteps = 0;
        int   sink = -1;

        while (true) {
            const float base = mv - u[i];
            const float* lrow = lc + i*NQ;

            // prefetch row slice
            float rv[NK];
            #pragma unroll
            for (int k = 0; k < NK; k++) {
                int j = k*32 + lane;
                rv[k] = (j < NQ) ? lrow[j] : INF;
            }

            // fused relax + local argmin (ascending j within lane keeps lowest-idx tie)
            float bv = INF; int bi = NQ;
            #pragma unroll
            for (int k = 0; k < NK; k++) {
                int j = k*32 + lane;
                if (j < NQ && !((sc >> k) & 1u)) {
                    float rr = base + rv[k] - vloc[k];
                    if (rr < shortest[k]) { shortest[k] = rr; path[j] = i; }
                    if (shortest[k] < bv) { bv = shortest[k]; bi = j; }
                }
            }

            // warp butterfly argmin, ties -> lowest column index (np.argmin)
            #pragma unroll
            for (int off = 16; off; off >>= 1) {
                float ov = __shfl_xor_sync(0xffffffffu, bv, off);
                int   oi = __shfl_xor_sync(0xffffffffu, bi, off);
                if (ov < bv || (ov == bv && oi < bi)) { bv = ov; bi = oi; }
            }
            mv = bv;
            const int fi = bi;
            if (lane == (fi & 31)) sc |= 1u << (fi >> 5);
            if (lane == 0) { selj[nsteps] = fi; selv[nsteps] = mv; }
            nsteps++;

            int r4 = row4col[fi];      // broadcast read
            if (r4 == -1) { sink = fi; break; }
            i = r4;
        }

        __syncwarp();   // selj/selv + path visible

        // dual updates (pre-augmentation row4col):
        //   u[curRow] += mv;  u[row4col[selj[s]]] += mv - selv[s] for non-sink steps
        if (lane == 0) u[curRow] += mv;
        for (int s = lane; s < nsteps - 1; s += 32) {
            int i2 = row4col[selj[s]];
            u[i2] += mv - selv[s];
        }
        // v[selj[s]] -= mv - selv[s]  (owning lane applies)
        for (int s = 0; s < nsteps; s++) {
            int j = selj[s];
            if ((j & 31) == lane) vloc[j >> 5] -= mv - selv[s];
        }
        __syncwarp();

        // augment (serial, tiny)
        if (lane == 0) {
            int j = sink;
            while (true) {
                int i2 = path[j];
                row4col[j] = i2;
                int nj = col4row[i2];
                col4row[i2] = j;
                j = nj;
                if (i2 == curRow) break;
            }
        }
        __syncwarp();
    }

    // emit indices sorted by query (rank counting)
    for (int t = lane; t < NT; t += 32) {
        int q = col4row[t];
        int rank = 0;
        #pragma unroll
        for (int t2 = 0; t2 < NT; t2++) rank += (col4row[t2] < q) ? 1 : 0;
        size_t base = (size_t)NROW * NCOL + (size_t)b * 2 * NT;
        out[base + rank]      = (float)q;
        out[base + NT + rank] = (float)t;
    }
}

// ---------------------------------------------------------
extern "C" void kernel_launch(void* const* d_in, const int* in_sizes, int n_in,
                              void* d_out, int out_size) {
    const float* pred_kp   = (const float*)d_in[0];  // (16,300,51)
    const float* pred_box  = (const float*)d_in[1];  // (16,300,6)
    const float* tgt_box   = (const float*)d_in[2];  // (16,50,6)
    const float* tgt_kp    = (const float*)d_in[3];  // (16,50,51)
    float* out = (float*)d_out;

    prep_kernel<<<(NCOL*KP3 + 255) / 256, 256>>>(tgt_box, tgt_kp);

    dim3 cg((NCOL + 255) / 256, NROW);
    cost_kernel<<<cg, 256>>>(pred_kp, pred_box, out);

    lap_kernel<<<BS, 32>>>(out);
}